// round 13
// baseline (speedup 1.0000x reference)
#include <cuda_runtime.h>
#include <math.h>

#define NUMR    100
#define BATCH   2048
#define NVAR    192
#define NEQC    30
#define NHDIM   222
#define MAXIT   15
#define SPB     8
#define NTHREADS 1024
#define PIF     3.14159265358979323846f

// shared memory float offsets (56224 floats = 224,896 B)
#define OFF_X    0        // 300*32 = 9600   [u][32]
#define OFF_Y    9600     // 300*48 = 14400  [u][48]
#define OFF_W    24000    // 300*48 = 14400  [u][48]
#define OFF_P    38400    // 48*36 = 1728
#define OFF_QS   40128    // 48*32 = 1536
#define OFF_M11  41664    // 1024 pair layout
#define OFF_MG2  42688    // 1024
#define OFF_DLP  43712    // 3*32*49 = 4704  [t*32+k][49]
#define OFF_PART 48416    // 8*16*49 = 6272  (6,7 = dc buffers)
#define OFF_PBV  54688    // 16*3*32 = 1536
#define SMEM_FLOATS 56224

typedef unsigned long long ull;

__device__ float M11Pg[1024];
__device__ float MG2Pg[1024];
__device__ float Gpart[8 * 1024];

__device__ __forceinline__ void fma2(ull& d, ull a, ull b) {
    asm("fma.rn.f32x2 %0, %1, %2, %0;" : "+l"(d) : "l"(a), "l"(b));
}
__device__ __forceinline__ float hadd2(ull v) {
    float lo, hi;
    asm("mov.b64 {%0, %1}, %2;" : "=f"(lo), "=f"(hi) : "l"(v));
    return lo + hi;
}
__device__ __forceinline__ float hadd2x2(ull a, ull b) {
    return hadd2(a) + hadd2(b);
}
__device__ __forceinline__ ull pack2(float v) {
    ull r; asm("mov.b64 %0, {%1, %1};" : "=l"(r) : "f"(v)); return r;
}
__device__ __forceinline__ void unpack2(float& lo, float& hi, ull v) {
    asm("mov.b64 {%0, %1}, %2;" : "=f"(lo), "=f"(hi) : "l"(v));
}

// prep1: per-CTA partial outer-product slabs
__global__ void prep_g(const float* __restrict__ Av,
                       const float* __restrict__ Aa,
                       const float* __restrict__ Ap)
{
    __shared__ float xs[38 * 32];
    int c = blockIdx.x;
    int tid = threadIdx.x;
    int u0 = c * 38;
    int u1 = (u0 + 38 < 300) ? u0 + 38 : 300;
    int len = u1 - u0;
    for (int idx = tid; idx < len * 32; idx += 1024) {
        int u = u0 + (idx >> 5);
        int col = idx & 31;
        int t = (u >= 100) + (u >= 200);
        const float* A = (t == 0) ? Av : ((t == 1) ? Aa : Ap);
        xs[idx] = A[(u - t * 100) * NVAR + col];
    }
    __syncthreads();
    int a = tid >> 5, b = tid & 31;
    float s0 = 0.f, s1 = 0.f;
#pragma unroll 2
    for (int i = 0; i < len; i += 2) {
        s0 += xs[i * 32 + a] * xs[i * 32 + b];
        if (i + 1 < len)
            s1 += xs[(i + 1) * 32 + a] * xs[(i + 1) * 32 + b];
    }
    Gpart[c * 1024 + tid] = s0 + s1;
}

// prep2: sum partials; M11 / M11G2 in pair layout
__global__ void prep_m(const float* __restrict__ Qi)
{
    __shared__ float g2s[1024];
    int tid = threadIdx.x;
    float acc = 0.f;
#pragma unroll
    for (int c = 0; c < 8; c++)
        acc += Gpart[c * 1024 + tid];
    g2s[tid] = 2.f * acc;
    __syncthreads();
    int pos = tid >> 5, k = tid & 31;
    float a0 = 0.f, a1 = 0.f;
#pragma unroll 4
    for (int j = 0; j < 32; j += 2) {
        a0 += Qi[pos * NHDIM + j]     * g2s[j * 32 + k];
        a1 += Qi[pos * NHDIM + j + 1] * g2s[(j + 1) * 32 + k];
    }
    int o = (k >> 1) * 64 + pos * 2 + (k & 1);
    MG2Pg[o] = a0 + a1;
    M11Pg[o] = Qi[pos * NHDIM + k];
}

__global__ void __launch_bounds__(NTHREADS, 1)
proj_filter_kernel(const float* __restrict__ lamda,
                   const float* __restrict__ c_in_g,
                   const float* __restrict__ c_samp,
                   const float* __restrict__ b_eq,
                   const float* __restrict__ Av,
                   const float* __restrict__ Aa,
                   const float* __restrict__ Ap,
                   const float* __restrict__ Qi,
                   float* __restrict__ out)
{
    extern __shared__ float sm[];
    const int tid   = threadIdx.x;
    const int warp  = tid >> 5;      // 0..31
    const int lane  = tid & 31;
    // state roles (warp < 16)
    const int samp  = warp >> 1;
    const int h     = warp & 1;
    const int mb    = 3 * h;
    const int s     = blockIdx.x * SPB + samp;
    const int col0  = samp * 6 + mb;
    const int col0s = samp * 6;

    // ---- stage X and the two 32x32 matrices ----
    for (int idx = tid; idx < 9600; idx += NTHREADS) {
        int t = idx / 3200;
        int rem = idx - t * 3200;
        const float* A = (t == 0) ? Av : ((t == 1) ? Aa : Ap);
        sm[OFF_X + idx] = A[(rem >> 5) * NVAR + (rem & 31)];
    }
    for (int idx = tid; idx < 2048; idx += NTHREADS) {
        if (idx < 1024) sm[OFF_M11 + idx] = M11Pg[idx];
        else            sm[OFF_MG2 + idx - 1024] = MG2Pg[idx - 1024];
    }

    // ---- per-sample state (warps 0-15 only) ----
    float cin[3], cprev[3], lsum[3], sdl[3];
    if (warp < 16) {
#pragma unroll
        for (int m = 0; m < 3; m++) {
            int j = (mb + m) * 32 + lane;
            cin[m]   = c_in_g[s * NVAR + j];
            cprev[m] = c_samp[s * NVAR + j];
            const float* lp = lamda + s * (3 * NVAR) + j;
            lsum[m] = lp[0] + lp[NVAR] + lp[2 * NVAR];
            float a = 0.f;
            const float* bq = b_eq + s * NEQC + (mb + m) * 5;
#pragma unroll
            for (int k = 0; k < 5; k++)
                a += Qi[lane * NHDIM + NVAR + k] * bq[k];
            sm[OFF_PBV + (warp * 3 + m) * 32 + lane] = a;   // pbv -> smem slab
        }
#pragma unroll
        for (int m = 0; m < 3; m++)
            sm[OFF_P + (col0 + m) * 36 + lane] = cprev[m];
    }
    __syncthreads();   // X, M11, MG2, P, PBV ready

    // ---- D0: y0 and w0 (split roles) ----
    if (warp >= 16) {
        // A-pass: cols 0-31
        int we = warp - 16;
        ull PA[16];
        const ulonglong2* PcA = (const ulonglong2*)&sm[OFF_P + lane * 36];
#pragma unroll
        for (int q = 0; q < 8; q++) {
            ulonglong2 a = PcA[q]; PA[2*q] = a.x; PA[2*q+1] = a.y;
        }
#pragma unroll
        for (int i = 0; i < 19; i++) {
            int u = we + 16 * i;
            if (u < 300) {
                int t = (u >= 100) + (u >= 200);
                float V = (t == 0) ? 0.8f : ((t == 1) ? 1.8f : PIF);
                const ulonglong2* Xr = (const ulonglong2*)&sm[OFF_X + u * 32];
                ull a0 = 0, a1 = 0;
#pragma unroll
                for (int q = 0; q < 8; q += 2) {
                    ulonglong2 x0 = Xr[q], x1 = Xr[q + 1];
                    fma2(a0, x0.x, PA[2*q]);   fma2(a0, x0.y, PA[2*q+1]);
                    fma2(a1, x1.x, PA[2*q+2]); fma2(a1, x1.y, PA[2*q+3]);
                }
                float yn = hadd2x2(a0, a1);
                sm[OFF_Y + u * 48 + lane] = yn;
                sm[OFF_W + u * 48 + lane] =
                    fmaxf(yn - V, 0.f) - fmaxf(-yn - V, 0.f);
            }
        }
    } else {
        // B-pass: cols 32-47, dual-row
        int bwe = warp;
        ull PB[16];
        const ulonglong2* PcB = (const ulonglong2*)&sm[OFF_P + (32 + (lane & 15)) * 36];
#pragma unroll
        for (int q = 0; q < 8; q++) {
            ulonglong2 b = PcB[q]; PB[2*q] = b.x; PB[2*q+1] = b.y;
        }
        int hoff = (lane >= 16) ? 16 : 0;
#pragma unroll
        for (int j = 0; j < 10; j++) {
            int u = bwe + 32 * j + hoff;
            bool valid = (u < 300);
            int uc = valid ? u : 0;
            int t = (uc >= 100) + (uc >= 200);
            float V = (t == 0) ? 0.8f : ((t == 1) ? 1.8f : PIF);
            const ulonglong2* Xr = (const ulonglong2*)&sm[OFF_X + uc * 32];
            ull b0 = 0, b1 = 0;
#pragma unroll
            for (int q = 0; q < 8; q += 2) {
                ulonglong2 x0 = Xr[q], x1 = Xr[q + 1];
                fma2(b0, x0.x, PB[2*q]);   fma2(b0, x0.y, PB[2*q+1]);
                fma2(b1, x1.x, PB[2*q+2]); fma2(b1, x1.y, PB[2*q+3]);
            }
            float yn = hadd2x2(b0, b1);
            if (valid) {
                sm[OFF_Y + uc * 48 + 32 + (lane & 15)] = yn;
                sm[OFF_W + uc * 48 + 32 + (lane & 15)] =
                    fmaxf(yn - V, 0.f) - fmaxf(-yn - V, 0.f);
            }
        }
    }
    __syncthreads();

    // ---- E0: dl0 partials (24 warps) ----
    if (warp < 12) {
        // B-cols dual-row: et, kq
        int et = warp >> 2, kq = warp & 3;
        ull dB[4] = {0,0,0,0};
        int hsel = lane >> 4;
        for (int i = 0; i < 50; i++) {
            int u = et * 100 + 2 * i + hsel;
            const ulonglong2* Xp = (const ulonglong2*)&sm[OFF_X + u * 32 + kq * 8];
            ull w = pack2(sm[OFF_W + u * 48 + 32 + (lane & 15)]);
            ulonglong2 x0 = Xp[0], x1 = Xp[1];
            fma2(dB[0], x0.x, w); fma2(dB[1], x0.y, w);
            fma2(dB[2], x1.x, w); fma2(dB[3], x1.y, w);
        }
        float f[8];
#pragma unroll
        for (int j = 0; j < 4; j++) unpack2(f[2*j], f[2*j+1], dB[j]);
#pragma unroll
        for (int r = 0; r < 8; r++)
            f[r] += __shfl_xor_sync(0xffffffffu, f[r], 16);
        if (lane < 16) {
#pragma unroll
            for (int r = 0; r < 8; r++)
                sm[OFF_DLP + (et * 32 + kq * 8 + r) * 49 + 32 + lane] = f[r];
        }
    } else if (warp < 24) {
        int aw = warp - 12;
        int et = aw >> 2, kq = aw & 3;
        ull dA[4] = {0,0,0,0};
        for (int u = et * 100; u < et * 100 + 100; u++) {
            const ulonglong2* Xp = (const ulonglong2*)&sm[OFF_X + u * 32 + kq * 8];
            ull w = pack2(sm[OFF_W + u * 48 + lane]);
            ulonglong2 x0 = Xp[0], x1 = Xp[1];
            fma2(dA[0], x0.x, w); fma2(dA[1], x0.y, w);
            fma2(dA[2], x1.x, w); fma2(dA[3], x1.y, w);
        }
#pragma unroll
        for (int j = 0; j < 4; j++) {
            float lo, hi;
            int base = OFF_DLP + (et * 32 + kq * 8 + 2 * j) * 49;
            unpack2(lo, hi, dA[j]);
            sm[base + lane] = lo;
            sm[base + 49 + lane] = hi;
        }
    }
    __syncthreads();

    // ---- sdl0 (warps 0-15) ----
    if (warp < 16) {
#pragma unroll
        for (int m = 0; m < 3; m++) sdl[m] = 0.f;
#pragma unroll
        for (int t = 0; t < 3; t++)
#pragma unroll
            for (int m = 0; m < 3; m++)
                sdl[m] += sm[OFF_DLP + (t * 32 + lane) * 49 + col0 + m];
    }

    float fp_sum = 0.f, rp_sum = 0.f;

    for (int it = 0; it < MAXIT; it++) {
        // ======== AB (warps 0-15): p_new = M11*qs + M11G2*p + pb ========
        if (warp < 16) {
            float dc = 0.f;
#pragma unroll
            for (int m = 0; m < 3; m++)
                sm[OFF_QS + (col0 + m) * 32 + lane] = lsum[m] + cin[m] - sdl[m];
            __syncwarp();
            ull a0m = 0, a0g = 0, a1m = 0, a1g = 0, a2m = 0, a2g = 0;
            const ull* M1 = (const ull*)&sm[OFF_M11];
            const ull* M2 = (const ull*)&sm[OFF_MG2];
            const ull* Q0 = (const ull*)&sm[OFF_QS + (col0    ) * 32];
            const ull* Q1 = (const ull*)&sm[OFF_QS + (col0 + 1) * 32];
            const ull* Q2 = (const ull*)&sm[OFF_QS + (col0 + 2) * 32];
            const ull* P0 = (const ull*)&sm[OFF_P  + (col0    ) * 36];
            const ull* P1 = (const ull*)&sm[OFF_P  + (col0 + 1) * 36];
            const ull* P2 = (const ull*)&sm[OFF_P  + (col0 + 2) * 36];
#pragma unroll 4
            for (int k2 = 0; k2 < 16; k2++) {
                ull mp = M1[k2 * 32 + lane];
                ull gp = M2[k2 * 32 + lane];
                fma2(a0m, mp, Q0[k2]); fma2(a0g, gp, P0[k2]);
                fma2(a1m, mp, Q1[k2]); fma2(a1g, gp, P1[k2]);
                fma2(a2m, mp, Q2[k2]); fma2(a2g, gp, P2[k2]);
            }
            float pn[3];
            pn[0] = hadd2x2(a0m, a0g) + sm[OFF_PBV + (warp * 3 + 0) * 32 + lane];
            pn[1] = hadd2x2(a1m, a1g) + sm[OFF_PBV + (warp * 3 + 1) * 32 + lane];
            pn[2] = hadd2x2(a2m, a2g) + sm[OFF_PBV + (warp * 3 + 2) * 32 + lane];
#pragma unroll
            for (int m = 0; m < 3; m++) {
                float dd = pn[m] - cprev[m];
                dc += dd * dd;
                cprev[m] = pn[m];
                sm[OFF_P + (col0 + m) * 36 + lane] = pn[m];
            }
            sm[OFF_PART + ((6 + (it & 1)) * 16 + warp) * 49 + lane] = dc;
        }
        __syncthreads();   // P_new ready                                  [bar1]

        // ======== D: split A-pass (warps 16-31) / B-pass (warps 0-15) ========
        if (warp >= 16) {
            int we = warp - 16;
            ull PA[16];
            const ulonglong2* PcA = (const ulonglong2*)&sm[OFF_P + lane * 36];
#pragma unroll
            for (int q = 0; q < 8; q++) {
                ulonglong2 a = PcA[q]; PA[2*q] = a.x; PA[2*q+1] = a.y;
            }
            float ra0 = 0.f, ra1 = 0.f, ra2 = 0.f;
            float da0 = 0.f, da1 = 0.f, da2 = 0.f;
#pragma unroll
            for (int i = 0; i < 19; i++) {
                int u = we + 16 * i;
                if (u < 300) {
                    int t = (u >= 100) + (u >= 200);
                    float V = (t == 0) ? 0.8f : ((t == 1) ? 1.8f : PIF);
                    const ulonglong2* Xr = (const ulonglong2*)&sm[OFF_X + u * 32];
                    ull a0 = 0, a1 = 0;
#pragma unroll
                    for (int q = 0; q < 8; q += 2) {
                        ulonglong2 x0 = Xr[q], x1 = Xr[q + 1];
                        fma2(a0, x0.x, PA[2*q]);   fma2(a0, x0.y, PA[2*q+1]);
                        fma2(a1, x1.x, PA[2*q+2]); fma2(a1, x1.y, PA[2*q+3]);
                    }
                    float yn = hadd2x2(a0, a1);
                    float yo = sm[OFF_Y + u * 48 + lane];
                    float rt = fmaxf(yn - V, 0.f), rb = fmaxf(-yn - V, 0.f);
                    float rr = rt * rt + rb * rb;
                    float d1 = fmaxf(V - yn, 0.f) - fmaxf(V - yo, 0.f);
                    float d2 = fmaxf(V + yn, 0.f) - fmaxf(V + yo, 0.f);
                    float dd = d1 * d1 + d2 * d2;
                    if (t == 0)      { ra0 += rr; da0 += dd; }
                    else if (t == 1) { ra1 += rr; da1 += dd; }
                    else             { ra2 += rr; da2 += dd; }
                    sm[OFF_Y + u * 48 + lane] = yn;
                    sm[OFF_W + u * 48 + lane] = rt - rb;
                }
            }
            sm[OFF_PART + ((0 * 3 + 0) * 16 + we) * 49 + lane] = ra0;
            sm[OFF_PART + ((0 * 3 + 1) * 16 + we) * 49 + lane] = ra1;
            sm[OFF_PART + ((0 * 3 + 2) * 16 + we) * 49 + lane] = ra2;
            sm[OFF_PART + ((1 * 3 + 0) * 16 + we) * 49 + lane] = da0;
            sm[OFF_PART + ((1 * 3 + 1) * 16 + we) * 49 + lane] = da1;
            sm[OFF_PART + ((1 * 3 + 2) * 16 + we) * 49 + lane] = da2;
        } else {
            int bwe = warp;
            ull PB[16];
            const ulonglong2* PcB = (const ulonglong2*)&sm[OFF_P + (32 + (lane & 15)) * 36];
#pragma unroll
            for (int q = 0; q < 8; q++) {
                ulonglong2 b = PcB[q]; PB[2*q] = b.x; PB[2*q+1] = b.y;
            }
            float ra0 = 0.f, ra1 = 0.f, ra2 = 0.f;
            float da0 = 0.f, da1 = 0.f, da2 = 0.f;
            int hoff = (lane >= 16) ? 16 : 0;
#pragma unroll
            for (int j = 0; j < 10; j++) {
                int u = bwe + 32 * j + hoff;
                bool valid = (u < 300);
                int uc = valid ? u : 0;
                int t = (uc >= 100) + (uc >= 200);
                float V = (t == 0) ? 0.8f : ((t == 1) ? 1.8f : PIF);
                const ulonglong2* Xr = (const ulonglong2*)&sm[OFF_X + uc * 32];
                ull b0 = 0, b1 = 0;
#pragma unroll
                for (int q = 0; q < 8; q += 2) {
                    ulonglong2 x0 = Xr[q], x1 = Xr[q + 1];
                    fma2(b0, x0.x, PB[2*q]);   fma2(b0, x0.y, PB[2*q+1]);
                    fma2(b1, x1.x, PB[2*q+2]); fma2(b1, x1.y, PB[2*q+3]);
                }
                float yn = hadd2x2(b0, b1);
                int yaddr = OFF_Y + uc * 48 + 32 + (lane & 15);
                float yo = sm[yaddr];
                float rt = fmaxf(yn - V, 0.f), rb = fmaxf(-yn - V, 0.f);
                float rr = rt * rt + rb * rb;
                float d1 = fmaxf(V - yn, 0.f) - fmaxf(V - yo, 0.f);
                float d2 = fmaxf(V + yn, 0.f) - fmaxf(V + yo, 0.f);
                float dd = d1 * d1 + d2 * d2;
                if (valid) {
                    if (t == 0)      { ra0 += rr; da0 += dd; }
                    else if (t == 1) { ra1 += rr; da1 += dd; }
                    else             { ra2 += rr; da2 += dd; }
                    sm[yaddr] = yn;
                    sm[OFF_W + uc * 48 + 32 + (lane & 15)] = rt - rb;
                }
            }
            ra0 += __shfl_xor_sync(0xffffffffu, ra0, 16);
            ra1 += __shfl_xor_sync(0xffffffffu, ra1, 16);
            ra2 += __shfl_xor_sync(0xffffffffu, ra2, 16);
            da0 += __shfl_xor_sync(0xffffffffu, da0, 16);
            da1 += __shfl_xor_sync(0xffffffffu, da1, 16);
            da2 += __shfl_xor_sync(0xffffffffu, da2, 16);
            if (lane < 16) {
                sm[OFF_PART + ((0 * 3 + 0) * 16 + bwe) * 49 + 32 + lane] = ra0;
                sm[OFF_PART + ((0 * 3 + 1) * 16 + bwe) * 49 + 32 + lane] = ra1;
                sm[OFF_PART + ((0 * 3 + 2) * 16 + bwe) * 49 + 32 + lane] = ra2;
                sm[OFF_PART + ((1 * 3 + 0) * 16 + bwe) * 49 + 32 + lane] = da0;
                sm[OFF_PART + ((1 * 3 + 1) * 16 + bwe) * 49 + 32 + lane] = da1;
                sm[OFF_PART + ((1 * 3 + 2) * 16 + bwe) * 49 + 32 + lane] = da2;
            }
        }
        __syncthreads();   // Y, W, partials ready                         [bar2]

        // ======== E: dl partials (24 warps; B dual-row / A full) ========
        if (warp < 12) {
            int et = warp >> 2, kq = warp & 3;
            ull dB[4] = {0,0,0,0};
            int hsel = lane >> 4;
            for (int i = 0; i < 50; i++) {
                int u = et * 100 + 2 * i + hsel;
                const ulonglong2* Xp = (const ulonglong2*)&sm[OFF_X + u * 32 + kq * 8];
                ull w = pack2(sm[OFF_W + u * 48 + 32 + (lane & 15)]);
                ulonglong2 x0 = Xp[0], x1 = Xp[1];
                fma2(dB[0], x0.x, w); fma2(dB[1], x0.y, w);
                fma2(dB[2], x1.x, w); fma2(dB[3], x1.y, w);
            }
            float f[8];
#pragma unroll
            for (int j = 0; j < 4; j++) unpack2(f[2*j], f[2*j+1], dB[j]);
#pragma unroll
            for (int r = 0; r < 8; r++)
                f[r] += __shfl_xor_sync(0xffffffffu, f[r], 16);
            if (lane < 16) {
#pragma unroll
                for (int r = 0; r < 8; r++)
                    sm[OFF_DLP + (et * 32 + kq * 8 + r) * 49 + 32 + lane] = f[r];
            }
        } else if (warp < 24) {
            int aw = warp - 12;
            int et = aw >> 2, kq = aw & 3;
            ull dA[4] = {0,0,0,0};
            for (int u = et * 100; u < et * 100 + 100; u++) {
                const ulonglong2* Xp = (const ulonglong2*)&sm[OFF_X + u * 32 + kq * 8];
                ull w = pack2(sm[OFF_W + u * 48 + lane]);
                ulonglong2 x0 = Xp[0], x1 = Xp[1];
                fma2(dA[0], x0.x, w); fma2(dA[1], x0.y, w);
                fma2(dA[2], x1.x, w); fma2(dA[3], x1.y, w);
            }
#pragma unroll
            for (int j = 0; j < 4; j++) {
                float lo, hi;
                int base = OFF_DLP + (et * 32 + kq * 8 + 2 * j) * 49;
                unpack2(lo, hi, dA[j]);
                sm[base + lane] = lo;
                sm[base + 49 + lane] = hi;
            }
        }
        __syncthreads();   // DLP ready                                    [bar3]

        // ======== F (warps 0-15): lsum/sdl + norms ========
        if (warp < 16) {
            float red[10];
#pragma unroll
            for (int m = 0; m < 3; m++) sdl[m] = 0.f;
#pragma unroll
            for (int t = 0; t < 3; t++) {
                float dls = 0.f;
#pragma unroll
                for (int c = 0; c < 6; c++) {
                    float dl = sm[OFF_DLP + (t * 32 + lane) * 49 + col0s + c];
                    dls += dl * dl;
                    if (c >= mb && c < mb + 3) {
                        lsum[c - mb] -= dl;
                        sdl[c - mb]  += dl;
                    }
                }
                red[6 + t] = dls;
            }
#pragma unroll
            for (int q = 0; q < 6; q++) {
                float v = 0.f;
                if (lane < 16) {
                    const float* pb_ = &sm[OFF_PART + (q * 16 + lane) * 49 + col0s];
                    v = pb_[0] + pb_[1] + pb_[2] + pb_[3] + pb_[4] + pb_[5];
                }
                red[q] = v;
            }
            red[9] = sm[OFF_PART + ((6 + (it & 1)) * 16 + warp) * 49 + lane]
                   + sm[OFF_PART + ((6 + (it & 1)) * 16 + (warp ^ 1)) * 49 + lane];

#pragma unroll
            for (int off = 16; off; off >>= 1)
#pragma unroll
                for (int q = 0; q < 10; q++)
                    red[q] += __shfl_xor_sync(0xffffffffu, red[q], off);

            rp_sum += sqrtf(red[0]) + sqrtf(red[1]) + sqrtf(red[2]);
            fp_sum += sqrtf(red[3]) + sqrtf(red[4]) + sqrtf(red[5])
                    + sqrtf(red[6]) + sqrtf(red[7]) + sqrtf(red[8]) + sqrtf(red[9]);
        }
        // no barrier: F reads PART/DLP; next writers (D/E) are past bar1/bar2
    }

    // ---- outputs ----
    if (warp < 16) {
#pragma unroll
        for (int m = 0; m < 3; m++)
            out[s * NVAR + (mb + m) * 32 + lane] = cprev[m];
        if (h == 0 && lane == 0) {
            out[BATCH * NVAR + s]         = fp_sum * (1.0f / MAXIT);
            out[BATCH * NVAR + BATCH + s] = rp_sum * (1.0f / MAXIT);
        }
    }
}

extern "C" void kernel_launch(void* const* d_in, const int* in_sizes, int n_in,
                              void* d_out, int out_size)
{
    const float* lamda = (const float*)d_in[0];
    const float* c_in  = (const float*)d_in[1];
    const float* c_s   = (const float*)d_in[2];
    const float* b_eq  = (const float*)d_in[3];
    const float* Av    = (const float*)d_in[4];
    const float* Aa    = (const float*)d_in[5];
    const float* Ap    = (const float*)d_in[6];
    const float* Qi    = (const float*)d_in[7];
    float* out = (float*)d_out;

    prep_g<<<8, 1024>>>(Av, Aa, Ap);
    prep_m<<<1, 1024>>>(Qi);

    int smem_bytes = SMEM_FLOATS * sizeof(float);
    cudaFuncSetAttribute(proj_filter_kernel,
                         cudaFuncAttributeMaxDynamicSharedMemorySize, smem_bytes);
    proj_filter_kernel<<<BATCH / SPB, NTHREADS, smem_bytes>>>(
        lamda, c_in, c_s, b_eq, Av, Aa, Ap, Qi, out);
}

// round 14
// speedup vs baseline: 1.0266x; 1.0266x over previous
#include <cuda_runtime.h>
#include <math.h>

#define NUMR    100
#define BATCH   2048
#define NVAR    192
#define NEQC    30
#define NHDIM   222
#define MAXIT   15
#define SPB     8
#define NTHREADS 512
#define PIF     3.14159265358979323846f

// shared memory float offsets (54688 floats = 218,752 B)
#define OFF_X    0        // 300*32 = 9600   [u][32]
#define OFF_Y    9600     // 300*48 = 14400  [u][48]
#define OFF_W    24000    // 300*48 = 14400  [u][48]
#define OFF_P    38400    // 48*36 = 1728
#define OFF_QS   40128    // 48*32 = 1536
#define OFF_M11  41664    // 1024 pair layout
#define OFF_MG2  42688    // 1024
#define OFF_DLP  43712    // 3*32*49 = 4704  [t*32+k][49]
#define OFF_PART 48416    // 8*16*49 = 6272  (6,7 = dc buffers)
#define SMEM_FLOATS 54688

typedef unsigned long long ull;

__device__ float M11Pg[1024];
__device__ float MG2Pg[1024];
__device__ float Gpart[8 * 1024];

__device__ __forceinline__ void fma2(ull& d, ull a, ull b) {
    asm("fma.rn.f32x2 %0, %1, %2, %0;" : "+l"(d) : "l"(a), "l"(b));
}
__device__ __forceinline__ float hadd2(ull v) {
    float lo, hi;
    asm("mov.b64 {%0, %1}, %2;" : "=f"(lo), "=f"(hi) : "l"(v));
    return lo + hi;
}
__device__ __forceinline__ float hadd2x2(ull a, ull b) {
    return hadd2(a) + hadd2(b);
}
__device__ __forceinline__ ull pack2(float v) {
    ull r; asm("mov.b64 %0, {%1, %1};" : "=l"(r) : "f"(v)); return r;
}
__device__ __forceinline__ void unpack2(float& lo, float& hi, ull v) {
    asm("mov.b64 {%0, %1}, %2;" : "=f"(lo), "=f"(hi) : "l"(v));
}

// prep1: per-CTA partial outer-product slabs (8 CTAs x 38 rows)
__global__ void prep_g(const float* __restrict__ Av,
                       const float* __restrict__ Aa,
                       const float* __restrict__ Ap)
{
    __shared__ float xs[38 * 32];
    int c = blockIdx.x;
    int tid = threadIdx.x;
    int u0 = c * 38;
    int u1 = (u0 + 38 < 300) ? u0 + 38 : 300;
    int len = u1 - u0;
    for (int idx = tid; idx < len * 32; idx += 1024) {
        int u = u0 + (idx >> 5);
        int col = idx & 31;
        int t = (u >= 100) + (u >= 200);
        const float* A = (t == 0) ? Av : ((t == 1) ? Aa : Ap);
        xs[idx] = A[(u - t * 100) * NVAR + col];
    }
    __syncthreads();
    int a = tid >> 5, b = tid & 31;
    float s0 = 0.f, s1 = 0.f;
#pragma unroll 2
    for (int i = 0; i < len; i += 2) {
        s0 += xs[i * 32 + a] * xs[i * 32 + b];
        if (i + 1 < len)
            s1 += xs[(i + 1) * 32 + a] * xs[(i + 1) * 32 + b];
    }
    Gpart[c * 1024 + tid] = s0 + s1;
}

// prep2: sum partials -> G2 (smem); M11 (pair layout) and M11G2 = M11 @ G2
__global__ void prep_m(const float* __restrict__ Qi)
{
    __shared__ float g2s[1024];
    int tid = threadIdx.x;
    float acc = 0.f;
#pragma unroll
    for (int c = 0; c < 8; c++)
        acc += Gpart[c * 1024 + tid];
    g2s[tid] = 2.f * acc;
    __syncthreads();
    int pos = tid >> 5, k = tid & 31;
    float a0 = 0.f, a1 = 0.f;
#pragma unroll 4
    for (int j = 0; j < 32; j += 2) {
        a0 += Qi[pos * NHDIM + j]     * g2s[j * 32 + k];
        a1 += Qi[pos * NHDIM + j + 1] * g2s[(j + 1) * 32 + k];
    }
    int o = (k >> 1) * 64 + pos * 2 + (k & 1);
    MG2Pg[o] = a0 + a1;
    M11Pg[o] = Qi[pos * NHDIM + k];
}

__global__ void __launch_bounds__(NTHREADS, 1)
proj_filter_kernel(const float* __restrict__ lamda,
                   const float* __restrict__ c_in_g,
                   const float* __restrict__ c_samp,
                   const float* __restrict__ b_eq,
                   const float* __restrict__ Av,
                   const float* __restrict__ Aa,
                   const float* __restrict__ Ap,
                   const float* __restrict__ Qi,
                   float* __restrict__ out)
{
    extern __shared__ float sm[];
    const int tid   = threadIdx.x;
    const int warp  = tid >> 5;
    const int lane  = tid & 31;
    const int samp  = warp >> 1;
    const int h     = warp & 1;
    const int mb    = 3 * h;
    const int s     = blockIdx.x * SPB + samp;
    const int col0  = samp * 6 + mb;
    const int col0s = samp * 6;

    // E role (warp<12): t block, kq 8-k chunk
    const int et = warp >> 2;
    const int kq = warp & 3;

    // ---- stage X and the two 32x32 matrices ----
    for (int idx = tid; idx < 9600; idx += NTHREADS) {
        int t = idx / 3200;
        int rem = idx - t * 3200;
        const float* A = (t == 0) ? Av : ((t == 1) ? Aa : Ap);
        sm[OFF_X + idx] = A[(rem >> 5) * NVAR + (rem & 31)];
    }
    for (int idx = tid; idx < 2048; idx += NTHREADS) {
        if (idx < 1024) sm[OFF_M11 + idx] = M11Pg[idx];
        else            sm[OFF_MG2 + idx - 1024] = MG2Pg[idx - 1024];
    }

    // ---- per-sample state ----
    float cin[3], cprev[3], lsum[3], sdl[3], pbv[3];
#pragma unroll
    for (int m = 0; m < 3; m++) {
        int j = (mb + m) * 32 + lane;
        cin[m]   = c_in_g[s * NVAR + j];
        cprev[m] = c_samp[s * NVAR + j];
        const float* lp = lamda + s * (3 * NVAR) + j;
        lsum[m] = lp[0] + lp[NVAR] + lp[2 * NVAR];
        float a = 0.f;
        const float* bq = b_eq + s * NEQC + (mb + m) * 5;
#pragma unroll
        for (int k = 0; k < 5; k++)
            a += Qi[lane * NHDIM + NVAR + k] * bq[k];
        pbv[m] = a;
    }

#pragma unroll
    for (int m = 0; m < 3; m++)
        sm[OFF_P + (col0 + m) * 36 + lane] = cprev[m];
    __syncthreads();   // X, M11, MG2, P ready

    // ---- D0: y0 and w0 ----
    {
        ull PA[16], PB[16];
        const ulonglong2* PcA = (const ulonglong2*)&sm[OFF_P + lane * 36];
        const ulonglong2* PcB = (const ulonglong2*)&sm[OFF_P + (32 + (lane & 15)) * 36];
#pragma unroll
        for (int q = 0; q < 8; q++) {
            ulonglong2 a = PcA[q]; PA[2*q] = a.x; PA[2*q+1] = a.y;
            ulonglong2 b = PcB[q]; PB[2*q] = b.x; PB[2*q+1] = b.y;
        }
#pragma unroll
        for (int i = 0; i < 19; i++) {
            int u = warp + 16 * i;
            if (u < 300) {
                int t = (u >= 100) + (u >= 200);
                float V = (t == 0) ? 0.8f : ((t == 1) ? 1.8f : PIF);
                const ulonglong2* Xr = (const ulonglong2*)&sm[OFF_X + u * 32];
                ull aA0 = 0, aA1 = 0, aB0 = 0, aB1 = 0;
#pragma unroll
                for (int q = 0; q < 8; q += 2) {
                    ulonglong2 x0 = Xr[q], x1 = Xr[q + 1];
                    fma2(aA0, x0.x, PA[2*q]);   fma2(aA0, x0.y, PA[2*q+1]);
                    fma2(aA1, x1.x, PA[2*q+2]); fma2(aA1, x1.y, PA[2*q+3]);
                    fma2(aB0, x0.x, PB[2*q]);   fma2(aB0, x0.y, PB[2*q+1]);
                    fma2(aB1, x1.x, PB[2*q+2]); fma2(aB1, x1.y, PB[2*q+3]);
                }
                float ynA = hadd2x2(aA0, aA1), ynB = hadd2x2(aB0, aB1);
                sm[OFF_Y + u * 48 + lane] = ynA;
                sm[OFF_W + u * 48 + lane] =
                    fmaxf(ynA - V, 0.f) - fmaxf(-ynA - V, 0.f);
                if (lane < 16) {
                    sm[OFF_Y + u * 48 + 32 + lane] = ynB;
                    sm[OFF_W + u * 48 + 32 + lane] =
                        fmaxf(ynB - V, 0.f) - fmaxf(-ynB - V, 0.f);
                }
            }
        }
    }
    __syncthreads();

    // ---- E0: dl0 partials from W ----
    if (warp < 12) {
        ull dA[4] = {0,0,0,0}, dB[4] = {0,0,0,0};
#pragma unroll 5
        for (int u = et * 100; u < et * 100 + 100; u++) {
            const ulonglong2* Xp = (const ulonglong2*)&sm[OFF_X + u * 32 + kq * 8];
            ull wA = pack2(sm[OFF_W + u * 48 + lane]);
            ull wB = pack2(sm[OFF_W + u * 48 + 32 + (lane & 15)]);
            ulonglong2 x0 = Xp[0], x1 = Xp[1];
            fma2(dA[0], x0.x, wA); fma2(dA[1], x0.y, wA);
            fma2(dA[2], x1.x, wA); fma2(dA[3], x1.y, wA);
            fma2(dB[0], x0.x, wB); fma2(dB[1], x0.y, wB);
            fma2(dB[2], x1.x, wB); fma2(dB[3], x1.y, wB);
        }
#pragma unroll
        for (int j = 0; j < 4; j++) {
            float lo, hi;
            int base = OFF_DLP + (et * 32 + kq * 8 + 2 * j) * 49;
            unpack2(lo, hi, dA[j]);
            sm[base + lane] = lo;
            sm[base + 49 + lane] = hi;
            if (lane < 16) {
                unpack2(lo, hi, dB[j]);
                sm[base + 32 + lane] = lo;
                sm[base + 49 + 32 + lane] = hi;
            }
        }
    }
    __syncthreads();

    // ---- sdl0 ----
#pragma unroll
    for (int m = 0; m < 3; m++) sdl[m] = 0.f;
#pragma unroll
    for (int t = 0; t < 3; t++)
#pragma unroll
        for (int m = 0; m < 3; m++)
            sdl[m] += sm[OFF_DLP + (t * 32 + lane) * 49 + col0 + m];

    float fp_sum = 0.f, rp_sum = 0.f;

    for (int it = 0; it < MAXIT; it++) {
        // ======== AB: p_new = M11*(lsum+cin-sdl) + M11G2*p + pb ========
        float dc = 0.f;
        {
#pragma unroll
            for (int m = 0; m < 3; m++)
                sm[OFF_QS + (col0 + m) * 32 + lane] = lsum[m] + cin[m] - sdl[m];
            __syncwarp();
            ull a0m = 0, a0g = 0, a1m = 0, a1g = 0, a2m = 0, a2g = 0;
            const ull* M1 = (const ull*)&sm[OFF_M11];
            const ull* M2 = (const ull*)&sm[OFF_MG2];
            const ull* Q0 = (const ull*)&sm[OFF_QS + (col0    ) * 32];
            const ull* Q1 = (const ull*)&sm[OFF_QS + (col0 + 1) * 32];
            const ull* Q2 = (const ull*)&sm[OFF_QS + (col0 + 2) * 32];
            const ull* P0 = (const ull*)&sm[OFF_P  + (col0    ) * 36];
            const ull* P1 = (const ull*)&sm[OFF_P  + (col0 + 1) * 36];
            const ull* P2 = (const ull*)&sm[OFF_P  + (col0 + 2) * 36];
#pragma unroll
            for (int k2 = 0; k2 < 16; k2++) {
                ull mp = M1[k2 * 32 + lane];
                ull gp = M2[k2 * 32 + lane];
                fma2(a0m, mp, Q0[k2]); fma2(a0g, gp, P0[k2]);
                fma2(a1m, mp, Q1[k2]); fma2(a1g, gp, P1[k2]);
                fma2(a2m, mp, Q2[k2]); fma2(a2g, gp, P2[k2]);
            }
            float pn[3];
            pn[0] = hadd2x2(a0m, a0g) + pbv[0];
            pn[1] = hadd2x2(a1m, a1g) + pbv[1];
            pn[2] = hadd2x2(a2m, a2g) + pbv[2];
#pragma unroll
            for (int m = 0; m < 3; m++) {
                float dd = pn[m] - cprev[m];
                dc += dd * dd;
                cprev[m] = pn[m];
                sm[OFF_P + (col0 + m) * 36 + lane] = pn[m];
            }
            sm[OFF_PART + ((6 + (it & 1)) * 16 + warp) * 49 + lane] = dc;
        }
        __syncthreads();   // P_new ready                                  [bar1]

        // ======== D: y/w update + res/ds partials (A and B interleaved) ========
        {
            ull PA[16], PB[16];
            const ulonglong2* PcA = (const ulonglong2*)&sm[OFF_P + lane * 36];
            const ulonglong2* PcB = (const ulonglong2*)&sm[OFF_P + (32 + (lane & 15)) * 36];
#pragma unroll
            for (int q = 0; q < 8; q++) {
                ulonglong2 a = PcA[q]; PA[2*q] = a.x; PA[2*q+1] = a.y;
                ulonglong2 b = PcB[q]; PB[2*q] = b.x; PB[2*q+1] = b.y;
            }
            float ra0A = 0.f, ra1A = 0.f, ra2A = 0.f;
            float da0A = 0.f, da1A = 0.f, da2A = 0.f;
            float ra0B = 0.f, ra1B = 0.f, ra2B = 0.f;
            float da0B = 0.f, da1B = 0.f, da2B = 0.f;
            int hoff = (lane >= 16) ? 16 : 0;
#pragma unroll
            for (int i = 0; i < 19; i++) {
                // ---- A row: cols 0-31, u = warp + 16i ----
                int u = warp + 16 * i;
                if (u < 300) {
                    int t = (u >= 100) + (u >= 200);
                    float V = (t == 0) ? 0.8f : ((t == 1) ? 1.8f : PIF);
                    const ulonglong2* Xr = (const ulonglong2*)&sm[OFF_X + u * 32];
                    ull aA0 = 0, aA1 = 0;
#pragma unroll
                    for (int q = 0; q < 8; q += 2) {
                        ulonglong2 x0 = Xr[q], x1 = Xr[q + 1];
                        fma2(aA0, x0.x, PA[2*q]);   fma2(aA0, x0.y, PA[2*q+1]);
                        fma2(aA1, x1.x, PA[2*q+2]); fma2(aA1, x1.y, PA[2*q+3]);
                    }
                    float yn = hadd2x2(aA0, aA1);
                    float yo = sm[OFF_Y + u * 48 + lane];
                    float rt = fmaxf(yn - V, 0.f), rb = fmaxf(-yn - V, 0.f);
                    float rr = rt * rt + rb * rb;
                    float d1 = fmaxf(V - yn, 0.f) - fmaxf(V - yo, 0.f);
                    float d2 = fmaxf(V + yn, 0.f) - fmaxf(V + yo, 0.f);
                    float dd = d1 * d1 + d2 * d2;
                    if (t == 0)      { ra0A += rr; da0A += dd; }
                    else if (t == 1) { ra1A += rr; da1A += dd; }
                    else             { ra2A += rr; da2A += dd; }
                    sm[OFF_Y + u * 48 + lane] = yn;
                    sm[OFF_W + u * 48 + lane] = rt - rb;
                }
                // ---- B rows (dual): cols 32-47, u = warp + 32j + hoff ----
                if (i < 10) {
                    int ub = warp + 32 * i + hoff;
                    bool valid = (ub < 300);
                    int uc = valid ? ub : 0;
                    int t = (uc >= 100) + (uc >= 200);
                    float V = (t == 0) ? 0.8f : ((t == 1) ? 1.8f : PIF);
                    const ulonglong2* Xr = (const ulonglong2*)&sm[OFF_X + uc * 32];
                    ull aB0 = 0, aB1 = 0;
#pragma unroll
                    for (int q = 0; q < 8; q += 2) {
                        ulonglong2 x0 = Xr[q], x1 = Xr[q + 1];
                        fma2(aB0, x0.x, PB[2*q]);   fma2(aB0, x0.y, PB[2*q+1]);
                        fma2(aB1, x1.x, PB[2*q+2]); fma2(aB1, x1.y, PB[2*q+3]);
                    }
                    float yn = hadd2x2(aB0, aB1);
                    int yaddr = OFF_Y + uc * 48 + 32 + (lane & 15);
                    float yo = sm[yaddr];
                    float rt = fmaxf(yn - V, 0.f), rb = fmaxf(-yn - V, 0.f);
                    float rr = rt * rt + rb * rb;
                    float d1 = fmaxf(V - yn, 0.f) - fmaxf(V - yo, 0.f);
                    float d2 = fmaxf(V + yn, 0.f) - fmaxf(V + yo, 0.f);
                    float dd = d1 * d1 + d2 * d2;
                    if (valid) {
                        if (t == 0)      { ra0B += rr; da0B += dd; }
                        else if (t == 1) { ra1B += rr; da1B += dd; }
                        else             { ra2B += rr; da2B += dd; }
                        sm[yaddr] = yn;
                        sm[OFF_W + uc * 48 + 32 + (lane & 15)] = rt - rb;
                    }
                }
            }
            ra0B += __shfl_xor_sync(0xffffffffu, ra0B, 16);
            ra1B += __shfl_xor_sync(0xffffffffu, ra1B, 16);
            ra2B += __shfl_xor_sync(0xffffffffu, ra2B, 16);
            da0B += __shfl_xor_sync(0xffffffffu, da0B, 16);
            da1B += __shfl_xor_sync(0xffffffffu, da1B, 16);
            da2B += __shfl_xor_sync(0xffffffffu, da2B, 16);

            sm[OFF_PART + ((0 * 3 + 0) * 16 + warp) * 49 + lane] = ra0A;
            sm[OFF_PART + ((0 * 3 + 1) * 16 + warp) * 49 + lane] = ra1A;
            sm[OFF_PART + ((0 * 3 + 2) * 16 + warp) * 49 + lane] = ra2A;
            sm[OFF_PART + ((1 * 3 + 0) * 16 + warp) * 49 + lane] = da0A;
            sm[OFF_PART + ((1 * 3 + 1) * 16 + warp) * 49 + lane] = da1A;
            sm[OFF_PART + ((1 * 3 + 2) * 16 + warp) * 49 + lane] = da2A;
            if (lane < 16) {
                sm[OFF_PART + ((0 * 3 + 0) * 16 + warp) * 49 + 32 + lane] = ra0B;
                sm[OFF_PART + ((0 * 3 + 1) * 16 + warp) * 49 + 32 + lane] = ra1B;
                sm[OFF_PART + ((0 * 3 + 2) * 16 + warp) * 49 + 32 + lane] = ra2B;
                sm[OFF_PART + ((1 * 3 + 0) * 16 + warp) * 49 + 32 + lane] = da0B;
                sm[OFF_PART + ((1 * 3 + 1) * 16 + warp) * 49 + 32 + lane] = da1B;
                sm[OFF_PART + ((1 * 3 + 2) * 16 + warp) * 49 + 32 + lane] = da2B;
            }
        }
        __syncthreads();   // Y, W, partials ready                         [bar2]

        // ======== E: dl partials from W (12 warps; unrolled x5 for MLP) ========
        if (warp < 12) {
            ull dA[4] = {0,0,0,0}, dB[4] = {0,0,0,0};
#pragma unroll 5
            for (int u = et * 100; u < et * 100 + 100; u++) {
                const ulonglong2* Xp = (const ulonglong2*)&sm[OFF_X + u * 32 + kq * 8];
                ull wA = pack2(sm[OFF_W + u * 48 + lane]);
                ull wB = pack2(sm[OFF_W + u * 48 + 32 + (lane & 15)]);
                ulonglong2 x0 = Xp[0], x1 = Xp[1];
                fma2(dA[0], x0.x, wA); fma2(dA[1], x0.y, wA);
                fma2(dA[2], x1.x, wA); fma2(dA[3], x1.y, wA);
                fma2(dB[0], x0.x, wB); fma2(dB[1], x0.y, wB);
                fma2(dB[2], x1.x, wB); fma2(dB[3], x1.y, wB);
            }
#pragma unroll
            for (int j = 0; j < 4; j++) {
                float lo, hi;
                int base = OFF_DLP + (et * 32 + kq * 8 + 2 * j) * 49;
                unpack2(lo, hi, dA[j]);
                sm[base + lane] = lo;
                sm[base + 49 + lane] = hi;
                if (lane < 16) {
                    unpack2(lo, hi, dB[j]);
                    sm[base + 32 + lane] = lo;
                    sm[base + 49 + 32 + lane] = hi;
                }
            }
        }
        __syncthreads();   // DLP ready                                    [bar3]

        // ======== F: lsum/sdl update + full-sample norms ========
        float red[10];
#pragma unroll
        for (int m = 0; m < 3; m++) sdl[m] = 0.f;
#pragma unroll
        for (int t = 0; t < 3; t++) {
            float dls = 0.f;
#pragma unroll
            for (int c = 0; c < 6; c++) {
                float dl = sm[OFF_DLP + (t * 32 + lane) * 49 + col0s + c];
                dls += dl * dl;
                if (c >= mb && c < mb + 3) {
                    lsum[c - mb] -= dl;
                    sdl[c - mb]  += dl;
                }
            }
            red[6 + t] = dls;
        }
#pragma unroll
        for (int q = 0; q < 6; q++) {
            float v = 0.f;
            if (lane < 16) {
                const float* pb_ = &sm[OFF_PART + (q * 16 + lane) * 49 + col0s];
                v = pb_[0] + pb_[1] + pb_[2] + pb_[3] + pb_[4] + pb_[5];
            }
            red[q] = v;
        }
        red[9] = sm[OFF_PART + ((6 + (it & 1)) * 16 + warp) * 49 + lane]
               + sm[OFF_PART + ((6 + (it & 1)) * 16 + (warp ^ 1)) * 49 + lane];

#pragma unroll
        for (int off = 16; off; off >>= 1)
#pragma unroll
            for (int q = 0; q < 10; q++)
                red[q] += __shfl_xor_sync(0xffffffffu, red[q], off);

        rp_sum += sqrtf(red[0]) + sqrtf(red[1]) + sqrtf(red[2]);
        fp_sum += sqrtf(red[3]) + sqrtf(red[4]) + sqrtf(red[5])
                + sqrtf(red[6]) + sqrtf(red[7]) + sqrtf(red[8]) + sqrtf(red[9]);
    }

    // ---- outputs ----
#pragma unroll
    for (int m = 0; m < 3; m++)
        out[s * NVAR + (mb + m) * 32 + lane] = cprev[m];
    if (h == 0 && lane == 0) {
        out[BATCH * NVAR + s]         = fp_sum * (1.0f / MAXIT);
        out[BATCH * NVAR + BATCH + s] = rp_sum * (1.0f / MAXIT);
    }
}

extern "C" void kernel_launch(void* const* d_in, const int* in_sizes, int n_in,
                              void* d_out, int out_size)
{
    const float* lamda = (const float*)d_in[0];
    const float* c_in  = (const float*)d_in[1];
    const float* c_s   = (const float*)d_in[2];
    const float* b_eq  = (const float*)d_in[3];
    const float* Av    = (const float*)d_in[4];
    const float* Aa    = (const float*)d_in[5];
    const float* Ap    = (const float*)d_in[6];
    const float* Qi    = (const float*)d_in[7];
    float* out = (float*)d_out;

    prep_g<<<8, 1024>>>(Av, Aa, Ap);
    prep_m<<<1, 1024>>>(Qi);

    int smem_bytes = SMEM_FLOATS * sizeof(float);
    cudaFuncSetAttribute(proj_filter_kernel,
                         cudaFuncAttributeMaxDynamicSharedMemorySize, smem_bytes);
    proj_filter_kernel<<<BATCH / SPB, NTHREADS, smem_bytes>>>(
        lamda, c_in, c_s, b_eq, Av, Aa, Ap, Qi, out);
}

// round 15
// speedup vs baseline: 1.0780x; 1.0500x over previous
#include <cuda_runtime.h>
#include <math.h>

#define NUMR    100
#define BATCH   2048
#define NVAR    192
#define NEQC    30
#define NHDIM   222
#define MAXIT   15
#define SPB     8
#define NTHREADS 512
#define PIF     3.14159265358979323846f

// shared memory float offsets (54688 floats = 218,752 B)
#define OFF_X    0        // 300*32 = 9600   [u][32]
#define OFF_Y    9600     // 300*48 = 14400  [u][48]
#define OFF_W    24000    // 300*48 = 14400  [u][48]
#define OFF_P    38400    // 48*36 = 1728
#define OFF_QS   40128    // 48*32 = 1536
#define OFF_M11  41664    // 1024 pair layout
#define OFF_MG2  42688    // 1024
#define OFF_DLP  43712    // 3*32*49 = 4704  [t*32+k][49]
#define OFF_PART 48416    // 8*16*49 = 6272  (6,7 = dc buffers)
#define SMEM_FLOATS 54688

typedef unsigned long long ull;

__device__ float M11Pg[1024];
__device__ float MG2Pg[1024];
__device__ float Gpart[8 * 1024];

__device__ __forceinline__ void fma2(ull& d, ull a, ull b) {
    asm("fma.rn.f32x2 %0, %1, %2, %0;" : "+l"(d) : "l"(a), "l"(b));
}
__device__ __forceinline__ float hadd2(ull v) {
    float lo, hi;
    asm("mov.b64 {%0, %1}, %2;" : "=f"(lo), "=f"(hi) : "l"(v));
    return lo + hi;
}
__device__ __forceinline__ float hadd2x2(ull a, ull b) {
    return hadd2(a) + hadd2(b);
}
__device__ __forceinline__ ull pack2(float v) {
    ull r; asm("mov.b64 %0, {%1, %1};" : "=l"(r) : "f"(v)); return r;
}
__device__ __forceinline__ void unpack2(float& lo, float& hi, ull v) {
    asm("mov.b64 {%0, %1}, %2;" : "=f"(lo), "=f"(hi) : "l"(v));
}

// prep1: per-CTA partial outer-product slabs (8 CTAs x 38 rows)
__global__ void prep_g(const float* __restrict__ Av,
                       const float* __restrict__ Aa,
                       const float* __restrict__ Ap)
{
    __shared__ float xs[38 * 32];
    int c = blockIdx.x;
    int tid = threadIdx.x;
    int u0 = c * 38;
    int u1 = (u0 + 38 < 300) ? u0 + 38 : 300;
    int len = u1 - u0;
    for (int idx = tid; idx < len * 32; idx += 1024) {
        int u = u0 + (idx >> 5);
        int col = idx & 31;
        int t = (u >= 100) + (u >= 200);
        const float* A = (t == 0) ? Av : ((t == 1) ? Aa : Ap);
        xs[idx] = A[(u - t * 100) * NVAR + col];
    }
    __syncthreads();
    int a = tid >> 5, b = tid & 31;
    float s0 = 0.f, s1 = 0.f;
#pragma unroll 2
    for (int i = 0; i < len; i += 2) {
        s0 += xs[i * 32 + a] * xs[i * 32 + b];
        if (i + 1 < len)
            s1 += xs[(i + 1) * 32 + a] * xs[(i + 1) * 32 + b];
    }
    Gpart[c * 1024 + tid] = s0 + s1;
}

// prep2: sum partials -> G2 (smem); M11 (pair layout) and M11G2 = M11 @ G2
__global__ void prep_m(const float* __restrict__ Qi)
{
    __shared__ float g2s[1024];
    int tid = threadIdx.x;
    float acc = 0.f;
#pragma unroll
    for (int c = 0; c < 8; c++)
        acc += Gpart[c * 1024 + tid];
    g2s[tid] = 2.f * acc;
    __syncthreads();
    int pos = tid >> 5, k = tid & 31;
    float a0 = 0.f, a1 = 0.f;
#pragma unroll 4
    for (int j = 0; j < 32; j += 2) {
        a0 += Qi[pos * NHDIM + j]     * g2s[j * 32 + k];
        a1 += Qi[pos * NHDIM + j + 1] * g2s[(j + 1) * 32 + k];
    }
    int o = (k >> 1) * 64 + pos * 2 + (k & 1);
    MG2Pg[o] = a0 + a1;
    M11Pg[o] = Qi[pos * NHDIM + k];
}

__global__ void __launch_bounds__(NTHREADS, 1)
proj_filter_kernel(const float* __restrict__ lamda,
                   const float* __restrict__ c_in_g,
                   const float* __restrict__ c_samp,
                   const float* __restrict__ b_eq,
                   const float* __restrict__ Av,
                   const float* __restrict__ Aa,
                   const float* __restrict__ Ap,
                   const float* __restrict__ Qi,
                   float* __restrict__ out)
{
    extern __shared__ float sm[];
    const int tid   = threadIdx.x;
    const int warp  = tid >> 5;
    const int lane  = tid & 31;
    const int samp  = warp >> 1;
    const int h     = warp & 1;
    const int mb    = 3 * h;
    const int s     = blockIdx.x * SPB + samp;
    const int col0  = samp * 6 + mb;
    const int col0s = samp * 6;

    // E role (warp<12): t block, kq 8-k chunk
    const int et = warp >> 2;
    const int kq = warp & 3;

    // ---- stage X and the two 32x32 matrices ----
    for (int idx = tid; idx < 9600; idx += NTHREADS) {
        int t = idx / 3200;
        int rem = idx - t * 3200;
        const float* A = (t == 0) ? Av : ((t == 1) ? Aa : Ap);
        sm[OFF_X + idx] = A[(rem >> 5) * NVAR + (rem & 31)];
    }
    for (int idx = tid; idx < 2048; idx += NTHREADS) {
        if (idx < 1024) sm[OFF_M11 + idx] = M11Pg[idx];
        else            sm[OFF_MG2 + idx - 1024] = MG2Pg[idx - 1024];
    }

    // ---- per-sample state ----
    float cin[3], cprev[3], lsum[3], sdl[3], pbv[3];
#pragma unroll
    for (int m = 0; m < 3; m++) {
        int j = (mb + m) * 32 + lane;
        cin[m]   = c_in_g[s * NVAR + j];
        cprev[m] = c_samp[s * NVAR + j];
        const float* lp = lamda + s * (3 * NVAR) + j;
        lsum[m] = lp[0] + lp[NVAR] + lp[2 * NVAR];
        float a = 0.f;
        const float* bq = b_eq + s * NEQC + (mb + m) * 5;
#pragma unroll
        for (int k = 0; k < 5; k++)
            a += Qi[lane * NHDIM + NVAR + k] * bq[k];
        pbv[m] = a;
    }

#pragma unroll
    for (int m = 0; m < 3; m++)
        sm[OFF_P + (col0 + m) * 36 + lane] = cprev[m];
    __syncthreads();   // X, M11, MG2, P ready

    // ---- D0: y0 and w0 ----
    {
        ull PA[16], PB[16];
        const ulonglong2* PcA = (const ulonglong2*)&sm[OFF_P + lane * 36];
        const ulonglong2* PcB = (const ulonglong2*)&sm[OFF_P + (32 + (lane & 15)) * 36];
#pragma unroll
        for (int q = 0; q < 8; q++) {
            ulonglong2 a = PcA[q]; PA[2*q] = a.x; PA[2*q+1] = a.y;
            ulonglong2 b = PcB[q]; PB[2*q] = b.x; PB[2*q+1] = b.y;
        }
#pragma unroll
        for (int i = 0; i < 19; i++) {
            int u = warp + 16 * i;
            if (u < 300) {
                int t = (u >= 100) + (u >= 200);
                float V = (t == 0) ? 0.8f : ((t == 1) ? 1.8f : PIF);
                const ulonglong2* Xr = (const ulonglong2*)&sm[OFF_X + u * 32];
                ull aA0 = 0, aA1 = 0, aB0 = 0, aB1 = 0;
#pragma unroll
                for (int q = 0; q < 8; q += 2) {
                    ulonglong2 x0 = Xr[q], x1 = Xr[q + 1];
                    fma2(aA0, x0.x, PA[2*q]);   fma2(aA0, x0.y, PA[2*q+1]);
                    fma2(aA1, x1.x, PA[2*q+2]); fma2(aA1, x1.y, PA[2*q+3]);
                    fma2(aB0, x0.x, PB[2*q]);   fma2(aB0, x0.y, PB[2*q+1]);
                    fma2(aB1, x1.x, PB[2*q+2]); fma2(aB1, x1.y, PB[2*q+3]);
                }
                float ynA = hadd2x2(aA0, aA1), ynB = hadd2x2(aB0, aB1);
                sm[OFF_Y + u * 48 + lane] = ynA;
                sm[OFF_W + u * 48 + lane] =
                    fmaxf(ynA - V, 0.f) - fmaxf(-ynA - V, 0.f);
                if (lane < 16) {
                    sm[OFF_Y + u * 48 + 32 + lane] = ynB;
                    sm[OFF_W + u * 48 + 32 + lane] =
                        fmaxf(ynB - V, 0.f) - fmaxf(-ynB - V, 0.f);
                }
            }
        }
    }
    __syncthreads();

    // ---- E0: dl0 partials from W ----
    if (warp < 12) {
        ull dA[4] = {0,0,0,0}, dB[4] = {0,0,0,0};
#pragma unroll 5
        for (int u = et * 100; u < et * 100 + 100; u++) {
            const ulonglong2* Xp = (const ulonglong2*)&sm[OFF_X + u * 32 + kq * 8];
            ull wA = pack2(sm[OFF_W + u * 48 + lane]);
            ull wB = pack2(sm[OFF_W + u * 48 + 32 + (lane & 15)]);
            ulonglong2 x0 = Xp[0], x1 = Xp[1];
            fma2(dA[0], x0.x, wA); fma2(dA[1], x0.y, wA);
            fma2(dA[2], x1.x, wA); fma2(dA[3], x1.y, wA);
            fma2(dB[0], x0.x, wB); fma2(dB[1], x0.y, wB);
            fma2(dB[2], x1.x, wB); fma2(dB[3], x1.y, wB);
        }
#pragma unroll
        for (int j = 0; j < 4; j++) {
            float lo, hi;
            int base = OFF_DLP + (et * 32 + kq * 8 + 2 * j) * 49;
            unpack2(lo, hi, dA[j]);
            sm[base + lane] = lo;
            sm[base + 49 + lane] = hi;
            if (lane < 16) {
                unpack2(lo, hi, dB[j]);
                sm[base + 32 + lane] = lo;
                sm[base + 49 + 32 + lane] = hi;
            }
        }
    }
    __syncthreads();

    // ---- sdl0 ----
#pragma unroll
    for (int m = 0; m < 3; m++) sdl[m] = 0.f;
#pragma unroll
    for (int t = 0; t < 3; t++)
#pragma unroll
        for (int m = 0; m < 3; m++)
            sdl[m] += sm[OFF_DLP + (t * 32 + lane) * 49 + col0 + m];

    float fp_sum = 0.f, rp_sum = 0.f;

    for (int it = 0; it < MAXIT; it++) {
        // ======== AB: p_new = M11*(lsum+cin-sdl) + M11G2*p + pb ========
        float dc = 0.f;
        {
#pragma unroll
            for (int m = 0; m < 3; m++)
                sm[OFF_QS + (col0 + m) * 32 + lane] = lsum[m] + cin[m] - sdl[m];
            __syncwarp();
            ull a0m = 0, a0g = 0, a1m = 0, a1g = 0, a2m = 0, a2g = 0;
            const ull* M1 = (const ull*)&sm[OFF_M11];
            const ull* M2 = (const ull*)&sm[OFF_MG2];
            const ull* Q0 = (const ull*)&sm[OFF_QS + (col0    ) * 32];
            const ull* Q1 = (const ull*)&sm[OFF_QS + (col0 + 1) * 32];
            const ull* Q2 = (const ull*)&sm[OFF_QS + (col0 + 2) * 32];
            const ull* P0 = (const ull*)&sm[OFF_P  + (col0    ) * 36];
            const ull* P1 = (const ull*)&sm[OFF_P  + (col0 + 1) * 36];
            const ull* P2 = (const ull*)&sm[OFF_P  + (col0 + 2) * 36];
#pragma unroll 4
            for (int k2 = 0; k2 < 16; k2++) {
                ull mp = M1[k2 * 32 + lane];
                ull gp = M2[k2 * 32 + lane];
                fma2(a0m, mp, Q0[k2]); fma2(a0g, gp, P0[k2]);
                fma2(a1m, mp, Q1[k2]); fma2(a1g, gp, P1[k2]);
                fma2(a2m, mp, Q2[k2]); fma2(a2g, gp, P2[k2]);
            }
            float pn[3];
            pn[0] = hadd2x2(a0m, a0g) + pbv[0];
            pn[1] = hadd2x2(a1m, a1g) + pbv[1];
            pn[2] = hadd2x2(a2m, a2g) + pbv[2];
#pragma unroll
            for (int m = 0; m < 3; m++) {
                float dd = pn[m] - cprev[m];
                dc += dd * dd;
                cprev[m] = pn[m];
                sm[OFF_P + (col0 + m) * 36 + lane] = pn[m];
            }
            sm[OFF_PART + ((6 + (it & 1)) * 16 + warp) * 49 + lane] = dc;
        }
        __syncthreads();   // P_new ready                                  [bar1]

        // ======== D: y/w update + res/ds partials ========
        {
            ull PA[16], PB[16];
            const ulonglong2* PcA = (const ulonglong2*)&sm[OFF_P + lane * 36];
            const ulonglong2* PcB = (const ulonglong2*)&sm[OFF_P + (32 + (lane & 15)) * 36];
#pragma unroll
            for (int q = 0; q < 8; q++) {
                ulonglong2 a = PcA[q]; PA[2*q] = a.x; PA[2*q+1] = a.y;
                ulonglong2 b = PcB[q]; PB[2*q] = b.x; PB[2*q+1] = b.y;
            }
            // ---- A-pass: cols 0-31, rows warp+16i ----
            float ra0A = 0.f, ra1A = 0.f, ra2A = 0.f;
            float da0A = 0.f, da1A = 0.f, da2A = 0.f;
#pragma unroll
            for (int i = 0; i < 19; i++) {
                int u = warp + 16 * i;
                if (u < 300) {
                    int t = (u >= 100) + (u >= 200);
                    float V = (t == 0) ? 0.8f : ((t == 1) ? 1.8f : PIF);
                    const ulonglong2* Xr = (const ulonglong2*)&sm[OFF_X + u * 32];
                    ull aA0 = 0, aA1 = 0;
#pragma unroll
                    for (int q = 0; q < 8; q += 2) {
                        ulonglong2 x0 = Xr[q], x1 = Xr[q + 1];
                        fma2(aA0, x0.x, PA[2*q]);   fma2(aA0, x0.y, PA[2*q+1]);
                        fma2(aA1, x1.x, PA[2*q+2]); fma2(aA1, x1.y, PA[2*q+3]);
                    }
                    float yn = hadd2x2(aA0, aA1);
                    float yo = sm[OFF_Y + u * 48 + lane];
                    float rt = fmaxf(yn - V, 0.f), rb = fmaxf(-yn - V, 0.f);
                    float rr = rt * rt + rb * rb;
                    float d1 = fmaxf(V - yn, 0.f) - fmaxf(V - yo, 0.f);
                    float d2 = fmaxf(V + yn, 0.f) - fmaxf(V + yo, 0.f);
                    float dd = d1 * d1 + d2 * d2;
                    if (t == 0)      { ra0A += rr; da0A += dd; }
                    else if (t == 1) { ra1A += rr; da1A += dd; }
                    else             { ra2A += rr; da2A += dd; }
                    sm[OFF_Y + u * 48 + lane] = yn;
                    sm[OFF_W + u * 48 + lane] = rt - rb;
                }
            }
            // ---- B-pass: cols 32-47, two rows per iter (per-half-warp) ----
            float ra0B = 0.f, ra1B = 0.f, ra2B = 0.f;
            float da0B = 0.f, da1B = 0.f, da2B = 0.f;
            int hoff = (lane >= 16) ? 16 : 0;
#pragma unroll
            for (int j = 0; j < 10; j++) {
                int u = warp + 32 * j + hoff;
                bool valid = (u < 300);
                int uc = valid ? u : 0;
                int t = (uc >= 100) + (uc >= 200);
                float V = (t == 0) ? 0.8f : ((t == 1) ? 1.8f : PIF);
                const ulonglong2* Xr = (const ulonglong2*)&sm[OFF_X + uc * 32];
                ull aB0 = 0, aB1 = 0;
#pragma unroll
                for (int q = 0; q < 8; q += 2) {
                    ulonglong2 x0 = Xr[q], x1 = Xr[q + 1];
                    fma2(aB0, x0.x, PB[2*q]);   fma2(aB0, x0.y, PB[2*q+1]);
                    fma2(aB1, x1.x, PB[2*q+2]); fma2(aB1, x1.y, PB[2*q+3]);
                }
                float yn = hadd2x2(aB0, aB1);
                int yaddr = OFF_Y + uc * 48 + 32 + (lane & 15);
                float yo = sm[yaddr];
                float rt = fmaxf(yn - V, 0.f), rb = fmaxf(-yn - V, 0.f);
                float rr = rt * rt + rb * rb;
                float d1 = fmaxf(V - yn, 0.f) - fmaxf(V - yo, 0.f);
                float d2 = fmaxf(V + yn, 0.f) - fmaxf(V + yo, 0.f);
                float dd = d1 * d1 + d2 * d2;
                if (valid) {
                    if (t == 0)      { ra0B += rr; da0B += dd; }
                    else if (t == 1) { ra1B += rr; da1B += dd; }
                    else             { ra2B += rr; da2B += dd; }
                    sm[yaddr] = yn;
                    sm[OFF_W + uc * 48 + 32 + (lane & 15)] = rt - rb;
                }
            }
            ra0B += __shfl_xor_sync(0xffffffffu, ra0B, 16);
            ra1B += __shfl_xor_sync(0xffffffffu, ra1B, 16);
            ra2B += __shfl_xor_sync(0xffffffffu, ra2B, 16);
            da0B += __shfl_xor_sync(0xffffffffu, da0B, 16);
            da1B += __shfl_xor_sync(0xffffffffu, da1B, 16);
            da2B += __shfl_xor_sync(0xffffffffu, da2B, 16);

            sm[OFF_PART + ((0 * 3 + 0) * 16 + warp) * 49 + lane] = ra0A;
            sm[OFF_PART + ((0 * 3 + 1) * 16 + warp) * 49 + lane] = ra1A;
            sm[OFF_PART + ((0 * 3 + 2) * 16 + warp) * 49 + lane] = ra2A;
            sm[OFF_PART + ((1 * 3 + 0) * 16 + warp) * 49 + lane] = da0A;
            sm[OFF_PART + ((1 * 3 + 1) * 16 + warp) * 49 + lane] = da1A;
            sm[OFF_PART + ((1 * 3 + 2) * 16 + warp) * 49 + lane] = da2A;
            if (lane < 16) {
                sm[OFF_PART + ((0 * 3 + 0) * 16 + warp) * 49 + 32 + lane] = ra0B;
                sm[OFF_PART + ((0 * 3 + 1) * 16 + warp) * 49 + 32 + lane] = ra1B;
                sm[OFF_PART + ((0 * 3 + 2) * 16 + warp) * 49 + 32 + lane] = ra2B;
                sm[OFF_PART + ((1 * 3 + 0) * 16 + warp) * 49 + 32 + lane] = da0B;
                sm[OFF_PART + ((1 * 3 + 1) * 16 + warp) * 49 + 32 + lane] = da1B;
                sm[OFF_PART + ((1 * 3 + 2) * 16 + warp) * 49 + 32 + lane] = da2B;
            }
        }
        __syncthreads();   // Y, W, partials ready                         [bar2]

        // ======== E: dl partials from W (12 warps; unrolled x5 for MLP) ========
        if (warp < 12) {
            ull dA[4] = {0,0,0,0}, dB[4] = {0,0,0,0};
#pragma unroll 5
            for (int u = et * 100; u < et * 100 + 100; u++) {
                const ulonglong2* Xp = (const ulonglong2*)&sm[OFF_X + u * 32 + kq * 8];
                ull wA = pack2(sm[OFF_W + u * 48 + lane]);
                ull wB = pack2(sm[OFF_W + u * 48 + 32 + (lane & 15)]);
                ulonglong2 x0 = Xp[0], x1 = Xp[1];
                fma2(dA[0], x0.x, wA); fma2(dA[1], x0.y, wA);
                fma2(dA[2], x1.x, wA); fma2(dA[3], x1.y, wA);
                fma2(dB[0], x0.x, wB); fma2(dB[1], x0.y, wB);
                fma2(dB[2], x1.x, wB); fma2(dB[3], x1.y, wB);
            }
#pragma unroll
            for (int j = 0; j < 4; j++) {
                float lo, hi;
                int base = OFF_DLP + (et * 32 + kq * 8 + 2 * j) * 49;
                unpack2(lo, hi, dA[j]);
                sm[base + lane] = lo;
                sm[base + 49 + lane] = hi;
                if (lane < 16) {
                    unpack2(lo, hi, dB[j]);
                    sm[base + 32 + lane] = lo;
                    sm[base + 49 + 32 + lane] = hi;
                }
            }
        }
        __syncthreads();   // DLP ready                                    [bar3]

        // ======== F: lsum/sdl update + full-sample norms ========
        float red[10];
#pragma unroll
        for (int m = 0; m < 3; m++) sdl[m] = 0.f;
#pragma unroll
        for (int t = 0; t < 3; t++) {
            float dls = 0.f;
#pragma unroll
            for (int c = 0; c < 6; c++) {
                float dl = sm[OFF_DLP + (t * 32 + lane) * 49 + col0s + c];
                dls += dl * dl;
                if (c >= mb && c < mb + 3) {
                    lsum[c - mb] -= dl;
                    sdl[c - mb]  += dl;
                }
            }
            red[6 + t] = dls;
        }
#pragma unroll
        for (int q = 0; q < 6; q++) {
            float v = 0.f;
            if (lane < 16) {
                const float* pb_ = &sm[OFF_PART + (q * 16 + lane) * 49 + col0s];
                v = pb_[0] + pb_[1] + pb_[2] + pb_[3] + pb_[4] + pb_[5];
            }
            red[q] = v;
        }
        red[9] = sm[OFF_PART + ((6 + (it & 1)) * 16 + warp) * 49 + lane]
               + sm[OFF_PART + ((6 + (it & 1)) * 16 + (warp ^ 1)) * 49 + lane];

#pragma unroll
        for (int off = 16; off; off >>= 1)
#pragma unroll
            for (int q = 0; q < 10; q++)
                red[q] += __shfl_xor_sync(0xffffffffu, red[q], off);

        rp_sum += sqrtf(red[0]) + sqrtf(red[1]) + sqrtf(red[2]);
        fp_sum += sqrtf(red[3]) + sqrtf(red[4]) + sqrtf(red[5])
                + sqrtf(red[6]) + sqrtf(red[7]) + sqrtf(red[8]) + sqrtf(red[9]);
    }

    // ---- outputs ----
#pragma unroll
    for (int m = 0; m < 3; m++)
        out[s * NVAR + (mb + m) * 32 + lane] = cprev[m];
    if (h == 0 && lane == 0) {
        out[BATCH * NVAR + s]         = fp_sum * (1.0f / MAXIT);
        out[BATCH * NVAR + BATCH + s] = rp_sum * (1.0f / MAXIT);
    }
}

extern "C" void kernel_launch(void* const* d_in, const int* in_sizes, int n_in,
                              void* d_out, int out_size)
{
    const float* lamda = (const float*)d_in[0];
    const float* c_in  = (const float*)d_in[1];
    const float* c_s   = (const float*)d_in[2];
    const float* b_eq  = (const float*)d_in[3];
    const float* Av    = (const float*)d_in[4];
    const float* Aa    = (const float*)d_in[5];
    const float* Ap    = (const float*)d_in[6];
    const float* Qi    = (const float*)d_in[7];
    float* out = (float*)d_out;

    prep_g<<<8, 1024>>>(Av, Aa, Ap);
    prep_m<<<1, 1024>>>(Qi);

    int smem_bytes = SMEM_FLOATS * sizeof(float);
    cudaFuncSetAttribute(proj_filter_kernel,
                         cudaFuncAttributeMaxDynamicSharedMemorySize, smem_bytes);
    proj_filter_kernel<<<BATCH / SPB, NTHREADS, smem_bytes>>>(
        lamda, c_in, c_s, b_eq, Av, Aa, Ap, Qi, out);
}